// round 14
// baseline (speedup 1.0000x reference)
#include <cuda_runtime.h>
#include <cuda_fp16.h>
#include <cstdint>

#define B_NODES 16384
#define L_HIST  50
#define D       64
#define LDW     72       // halves per row (144 B) for all f16 matrices
#define NPI     2        // nodes per iteration (one per 4-warp group)
#define MROWS   128
#define VROWS   100
#define NI      100000
#define NR      5
#define GRID    296
#define STRIDE  (GRID * NPI)

// Scratch (module-static device memory; allocation-free at launch time)
__device__ __half g_h_pre[NI * D];       // f16( f16MMA(v2e) @ W1_top )
__device__ __half g_r_pre[NR * D];       // f16( r2e_w @ W1_bot + b1 )
__device__ float  g_u_att[B_NODES * D];  // per-node att1 uv-half + b_a1 (f32)

// ---------------------------------------------------------------------------
// mma + ldmatrix helpers
// ---------------------------------------------------------------------------
__device__ __forceinline__ void mma_f16(float (&d)[4],
                                        uint32_t a0, uint32_t a1, uint32_t a2, uint32_t a3,
                                        uint32_t b0, uint32_t b1)
{
    asm volatile(
        "mma.sync.aligned.m16n8k16.row.col.f32.f16.f16.f32 "
        "{%0,%1,%2,%3}, {%4,%5,%6,%7}, {%8,%9}, {%0,%1,%2,%3};\n"
        : "+f"(d[0]), "+f"(d[1]), "+f"(d[2]), "+f"(d[3])
        : "r"(a0), "r"(a1), "r"(a2), "r"(a3), "r"(b0), "r"(b1));
}

__device__ __forceinline__ void ldsm_x4(uint32_t (&r)[4], uint32_t addr) {
    asm volatile("ldmatrix.sync.aligned.m8n8.x4.shared.b16 {%0,%1,%2,%3}, [%4];"
                 : "=r"(r[0]), "=r"(r[1]), "=r"(r[2]), "=r"(r[3]) : "r"(addr));
}

// Load a warp's B fragments (n-slice nbk..nbk+31, all k) into registers.
__device__ __forceinline__ void load_bfrag(
    const __half* __restrict__ Wt, uint32_t (&bc)[4][8], int nbk, int lane)
{
    uint32_t bbase = (uint32_t)__cvta_generic_to_shared(Wt)
                   + (uint32_t)((((nbk + ((lane >> 4) << 3) + (lane & 7)) * LDW)
                                 + (((lane >> 3) & 1) << 3)) << 1);
    #pragma unroll
    for (int ks = 0; ks < 4; ks++) {
        uint32_t b0[4], b1[4];
        ldsm_x4(b0, bbase + 32 * ks);
        ldsm_x4(b1, bbase + 32 * ks + 32 * LDW);
        bc[ks][0] = b0[0]; bc[ks][1] = b0[1]; bc[ks][2] = b0[2]; bc[ks][3] = b0[3];
        bc[ks][4] = b1[0]; bc[ks][5] = b1[1]; bc[ks][6] = b1[2]; bc[ks][7] = b1[3];
    }
}

// 64x64x64 GEMM slice with register-cached B fragments; warp tile 32x32.
__device__ __forceinline__ void run_mma_gemm_cb(
    const __half* __restrict__ Ab, const uint32_t (&bc)[4][8],
    float (&acc)[2][4][4], int mb, int lane)
{
    uint32_t abase = (uint32_t)__cvta_generic_to_shared(Ab)
                   + (uint32_t)((((mb + (lane & 15)) * LDW) + ((lane >> 4) << 3)) << 1);
    #pragma unroll
    for (int ks = 0; ks < 4; ks++) {
        uint32_t a0[4], a1[4];
        ldsm_x4(a0, abase + 32 * ks);
        ldsm_x4(a1, abase + 32 * ks + 32 * LDW);
        mma_f16(acc[0][0], a0[0], a0[1], a0[2], a0[3], bc[ks][0], bc[ks][1]);
        mma_f16(acc[0][1], a0[0], a0[1], a0[2], a0[3], bc[ks][2], bc[ks][3]);
        mma_f16(acc[0][2], a0[0], a0[1], a0[2], a0[3], bc[ks][4], bc[ks][5]);
        mma_f16(acc[0][3], a0[0], a0[1], a0[2], a0[3], bc[ks][6], bc[ks][7]);
        mma_f16(acc[1][0], a1[0], a1[1], a1[2], a1[3], bc[ks][0], bc[ks][1]);
        mma_f16(acc[1][1], a1[0], a1[1], a1[2], a1[3], bc[ks][2], bc[ks][3]);
        mma_f16(acc[1][2], a1[0], a1[1], a1[2], a1[3], bc[ks][4], bc[ks][5]);
        mma_f16(acc[1][3], a1[0], a1[1], a1[2], a1[3], bc[ks][6], bc[ks][7]);
    }
}

// Same but with B from shared memory (GEMM C).
__device__ __forceinline__ void run_mma_gemm_sb(
    const __half* __restrict__ Ab, const __half* __restrict__ Wt,
    float (&acc)[2][4][4], int mb, int nbk, int lane)
{
    uint32_t abase = (uint32_t)__cvta_generic_to_shared(Ab)
                   + (uint32_t)((((mb + (lane & 15)) * LDW) + ((lane >> 4) << 3)) << 1);
    uint32_t bbase = (uint32_t)__cvta_generic_to_shared(Wt)
                   + (uint32_t)((((nbk + ((lane >> 4) << 3) + (lane & 7)) * LDW)
                                 + (((lane >> 3) & 1) << 3)) << 1);
    #pragma unroll
    for (int ks = 0; ks < 4; ks++) {
        uint32_t a0[4], a1[4], b0[4], b1[4];
        ldsm_x4(a0, abase + 32 * ks);
        ldsm_x4(a1, abase + 32 * ks + 32 * LDW);
        ldsm_x4(b0, bbase + 32 * ks);
        ldsm_x4(b1, bbase + 32 * ks + 32 * LDW);
        mma_f16(acc[0][0], a0[0], a0[1], a0[2], a0[3], b0[0], b0[1]);
        mma_f16(acc[0][1], a0[0], a0[1], a0[2], a0[3], b0[2], b0[3]);
        mma_f16(acc[0][2], a0[0], a0[1], a0[2], a0[3], b1[0], b1[1]);
        mma_f16(acc[0][3], a0[0], a0[1], a0[2], a0[3], b1[2], b1[3]);
        mma_f16(acc[1][0], a1[0], a1[1], a1[2], a1[3], b0[0], b0[1]);
        mma_f16(acc[1][1], a1[0], a1[1], a1[2], a1[3], b0[2], b0[3]);
        mma_f16(acc[1][2], a1[0], a1[1], a1[2], a1[3], b1[0], b1[1]);
        mma_f16(acc[1][3], a1[0], a1[1], a1[2], a1[3], b1[2], b1[3]);
    }
}

// relu + f16 store of the 32x32 warp tile into Out[64][LDW]
__device__ __forceinline__ void store_relu_f16(
    __half* __restrict__ Out, float (&acc)[2][4][4],
    int mb, int nbk, int g, int q)
{
    #pragma unroll
    for (int mt = 0; mt < 2; mt++)
        #pragma unroll
        for (int nt = 0; nt < 4; nt++) {
            int r0 = mb + 16 * mt + g;
            int c  = nbk + 8 * nt + 2 * q;
            __half2 v0 = __floats2half2_rn(fmaxf(acc[mt][nt][0], 0.f),
                                           fmaxf(acc[mt][nt][1], 0.f));
            __half2 v1 = __floats2half2_rn(fmaxf(acc[mt][nt][2], 0.f),
                                           fmaxf(acc[mt][nt][3], 0.f));
            *(__half2*)(Out + r0 * LDW + c)       = v0;
            *(__half2*)(Out + (r0 + 8) * LDW + c) = v1;
        }
}

__device__ __forceinline__ void cp_async16(uint32_t dst, const void* src) {
    asm volatile("cp.async.cg.shared.global [%0], [%1], 16;"
                 :: "r"(dst), "l"(src) : "memory");
}

// ---------------------------------------------------------------------------
// Precompute 1: h_pre = f16MMA(v2e @ W1_top); block 0 also does r_pre (f16)
// ---------------------------------------------------------------------------
__global__ void __launch_bounds__(256)
pre_h_kernel(const float* __restrict__ v2e,
             const float* __restrict__ w1,
             const float* __restrict__ r2e,
             const float* __restrict__ b1)
{
    __shared__ __align__(16) __half W1t[D * LDW];
    __shared__ __align__(16) __half As[MROWS * LDW];
    const int t = threadIdx.x;
    const int wid = t >> 5, lane = t & 31;
    const int g = lane >> 2, q = lane & 3;
    const int mb = (wid & 3) * 32, nbk = (wid >> 2) * 32;
    const int base = blockIdx.x * MROWS;

    for (int i = t; i < D * D; i += 256) {
        int n = i >> 6, k = i & 63;
        W1t[n * LDW + k] = __float2half_rn(w1[k * D + n]);
    }
    for (int idx = t; idx < MROWS * 16; idx += 256) {
        int r = idx >> 4, c4 = (idx & 15) << 2;
        int row = base + r; if (row >= NI) row = NI - 1;
        float4 v = *(const float4*)(v2e + (size_t)row * D + c4);
        *(__half2*)(As + r * LDW + c4)     = __floats2half2_rn(v.x, v.y);
        *(__half2*)(As + r * LDW + c4 + 2) = __floats2half2_rn(v.z, v.w);
    }
    __syncthreads();

    float acc[2][4][4];
    #pragma unroll
    for (int mt = 0; mt < 2; mt++)
        #pragma unroll
        for (int nt = 0; nt < 4; nt++)
            #pragma unroll
            for (int e = 0; e < 4; e++) acc[mt][nt][e] = 0.f;
    run_mma_gemm_sb(As, W1t, acc, mb, nbk, lane);

    #pragma unroll
    for (int mt = 0; mt < 2; mt++)
        #pragma unroll
        for (int nt = 0; nt < 4; nt++) {
            int r0 = base + mb + 16 * mt + g;
            int c  = nbk + 8 * nt + 2 * q;
            if (r0 < NI)
                *(__half2*)(g_h_pre + (size_t)r0 * D + c) =
                    __floats2half2_rn(acc[mt][nt][0], acc[mt][nt][1]);
            if (r0 + 8 < NI)
                *(__half2*)(g_h_pre + (size_t)(r0 + 8) * D + c) =
                    __floats2half2_rn(acc[mt][nt][2], acc[mt][nt][3]);
        }

    if (blockIdx.x == 0) {
        for (int i = t; i < NR * D; i += 256) {
            int r = i >> 6, j = i & 63;
            float a = b1[j];
            #pragma unroll 16
            for (int k = 0; k < D; k++)
                a = fmaf(r2e[r * D + k], w1[(D + k) * D + j], a);
            g_r_pre[i] = __float2half_rn(a);
        }
    }
}

// ---------------------------------------------------------------------------
// Precompute 2: u_att[b][j] = u2e[nodes[b]] @ A1_bot[:,j] + b_a1[j]  (f32)
// grid 256, block 256: each block handles 64 nodes (4 per pass x 16 passes)
// ---------------------------------------------------------------------------
__global__ void __launch_bounds__(256)
pre_u_kernel(const int* __restrict__ nodes,
             const float* __restrict__ u2e,
             const float* __restrict__ a1w,
             const float* __restrict__ a1b)
{
    __shared__ float A1B[D * D];
    const int t = threadIdx.x;
    for (int i = t; i < D * D; i += 256) A1B[i] = a1w[D * D + i];
    __syncthreads();

    const int j   = t & 63;
    const int sub = t >> 6;                 // 0..3
    const int base = blockIdx.x * 64;
    const float bj = a1b[j];
    #pragma unroll 1
    for (int p = 0; p < 16; p++) {
        int b = base + p * 4 + sub;
        const float* uv = u2e + (size_t)nodes[b] * D;
        float acc = bj;
        #pragma unroll 16
        for (int k = 0; k < D; k++)
            acc = fmaf(uv[k], A1B[k * D + j], acc);
        g_u_att[(size_t)b * D + j] = acc;
    }
}

// ---------------------------------------------------------------------------
// Main persistent kernel: two independent 4-warp groups per CTA, one node each
// ---------------------------------------------------------------------------
struct __align__(16) Smem {
    __half W2s[D * LDW];        // w_r2_w^T   [n][k]
    __half A1ts[D * LDW];       // att1_w top^T [n][k]
    __half A2s[D * LDW];        // att2_w^T   [n][k]
    __half Hbuf[MROWS * LDW];   // activations; rows [gid*64, gid*64+64)
    __half Obuf[MROWS * LDW];   // o_history f16
    __half rpre[NR * D];        // f16
    float  a3s[D];
    float  b_r2[D];
    float  b_a2[D];
    float  u_att[NPI * D];      // cp.async-landed per-node att bias (f32)
    float  lpart[MROWS * 2];    // per-row logit partials (2 col-warp-groups)
    float  attw[MROWS];
    float  outp[4 * D];         // [gid*2 + mbblk][64]
    int    items[VROWS];        // [gid*50 + l]
    int    rats[VROWS];
};

#define GROUP_BAR() asm volatile("bar.sync %0, 128;" :: "r"(gid + 1) : "memory")

__global__ void __launch_bounds__(256, 2)
uv_agg_main(const int* __restrict__ huv,
            const int* __restrict__ hr,
            const float* __restrict__ w2w, const float* __restrict__ w2b,
            const float* __restrict__ a1w,
            const float* __restrict__ a2w, const float* __restrict__ a2b,
            const float* __restrict__ a3w,
            float* __restrict__ out)
{
    extern __shared__ __align__(16) char sraw[];
    Smem& s = *reinterpret_cast<Smem*>(sraw);
    const int t    = threadIdx.x;
    const int gid  = t >> 7;          // group (node) 0/1
    const int gt   = t & 127;         // thread-in-group
    const int wg   = (t >> 5) & 3;    // warp-in-group 0..3
    const int lane = t & 31;
    const int g    = lane >> 2;
    const int q    = lane & 3;
    const int mb   = (wg & 1) * 32;   // row-block within the node's 64-row tile
    const int nbk  = (wg >> 1) * 32;  // col-block
    const int cw   = wg >> 1;
    const int rowbase = gid * 64;
    const uint32_t hbuf_u32 = (uint32_t)__cvta_generic_to_shared(s.Hbuf);
    const uint32_t uatt_u32 = (uint32_t)__cvta_generic_to_shared(s.u_att);

    __half* Hg = s.Hbuf + rowbase * LDW;
    __half* Og = s.Obuf + rowbase * LDW;

    // ---- one-time weight staging (all 256 threads) ----
    for (int i = t; i < 3 * D * D; i += 256) {
        int mat = i >> 12, w = i & 4095;
        int n = w >> 6, k = w & 63;
        const float* W = (mat == 0) ? w2w : (mat == 1) ? a1w : a2w;
        __half h = __float2half_rn(W[k * D + n]);
        if (mat == 0)      s.W2s [n * LDW + k] = h;
        else if (mat == 1) s.A1ts[n * LDW + k] = h;
        else               s.A2s [n * LDW + k] = h;
    }
    if (t < D) {
        s.a3s[t]  = a3w[t];
        s.b_r2[t] = w2b[t];
        s.b_a2[t] = a2b[t];
    }
    for (int i = t; i < NR * D; i += 256) s.rpre[i] = g_r_pre[i];
    // zero Hbuf/Obuf so garbage f16 rows can never be NaN/inf
    for (int i = t; i < MROWS * LDW / 2; i += 256) {
        ((uint32_t*)s.Hbuf)[i] = 0u;
        ((uint32_t*)s.Obuf)[i] = 0u;
    }
    __syncthreads();

    // ---- per-warp register B caches (GEMM A + GEMM B) ----
    uint32_t bcW2[4][8], bcA1[4][8];
    load_bfrag(s.W2s,  bcW2, nbk, lane);
    load_bfrag(s.A1ts, bcA1, nbk, lane);

    // ---- prologue: iter-0 indices ----
    const int nb0 = blockIdx.x * NPI;
    if (t < VROWS) {
        int node = (t >= L_HIST);
        int l = t - L_HIST * node;
        int gi = (nb0 + node) * L_HIST + l;
        s.items[node * L_HIST + l] = huv[gi];
        s.rats[node * L_HIST + l]  = hr[gi];
    }
    __syncthreads();

    // ---- prologue: cp.async iter-0 h_pre rows -> Hbuf ; u_att rows ----
    for (int c = t; c < VROWS * 8; c += 256) {
        int v = c >> 3, k8 = (c & 7) << 3;
        int node = (v >= L_HIST);
        int r = node * 64 + (v - L_HIST * node);
        cp_async16(hbuf_u32 + (uint32_t)(r * LDW + k8) * 2,
                   g_h_pre + (size_t)s.items[v] * D + k8);
    }
    if (t < 32) {
        int node = t >> 4, ch = t & 15;
        cp_async16(uatt_u32 + (uint32_t)(node * D + ch * 4) * 4,
                   g_u_att + (size_t)(nb0 + node) * D + ch * 4);
    }
    asm volatile("cp.async.commit_group;" ::: "memory");
    asm volatile("cp.async.wait_group 0;" ::: "memory");
    __syncthreads();

    // ================= per-group pipeline (groups desynchronized) =========
    for (int nb = nb0; nb < B_NODES; nb += STRIDE) {
        const int node_g = nb + gid;
        const int nb2    = nb + STRIDE;
        const bool pf    = nb2 < B_NODES;

        // ---- phase 0: in-place Hg = relu(Hg + rpre) (valid rows) ----
        {
            const __half2 zero2 = __floats2half2_rn(0.f, 0.f);
            for (int c = gt; c < L_HIST * 8; c += 128) {
                int v = c >> 3, c8 = (c & 7) << 3;
                __half* hp = Hg + v * LDW + c8;
                const __half* rp = s.rpre + s.rats[gid * L_HIST + v] * D + c8;
                uint2 hv  = *(const uint2*)hp;
                uint2 hv2 = *(const uint2*)(hp + 4);
                uint2 rv  = *(const uint2*)rp;
                uint2 rv2 = *(const uint2*)(rp + 4);
                __half2 o[4];
                o[0] = __hmax2(__hadd2(*(__half2*)&hv.x,  *(__half2*)&rv.x),  zero2);
                o[1] = __hmax2(__hadd2(*(__half2*)&hv.y,  *(__half2*)&rv.y),  zero2);
                o[2] = __hmax2(__hadd2(*(__half2*)&hv2.x, *(__half2*)&rv2.x), zero2);
                o[3] = __hmax2(__hadd2(*(__half2*)&hv2.y, *(__half2*)&rv2.y), zero2);
                *(float4*)hp = *(float4*)o;
            }
        }
        GROUP_BAR();

        float acc[2][4][4];

        // ---- phase 1: GEMM A (cached W2) -> Og ----
        #pragma unroll
        for (int mt = 0; mt < 2; mt++)
            #pragma unroll
            for (int nt = 0; nt < 4; nt++) {
                int c = nbk + 8 * nt + 2 * q;
                float b0 = s.b_r2[c], b1 = s.b_r2[c + 1];
                acc[mt][nt][0] = b0; acc[mt][nt][1] = b1;
                acc[mt][nt][2] = b0; acc[mt][nt][3] = b1;
            }
        run_mma_gemm_cb(Hg, bcW2, acc, mb, lane);
        store_relu_f16(Og, acc, mb, nbk, g, q);
        GROUP_BAR();

        // ---- phase 2: idx prefetch (regs) ; GEMM B (cached A1t) -> Hg ----
        int it2 = 0, rt2 = 0;
        if (gt < L_HIST) {
            int gi = pf ? ((nb2 + gid) * L_HIST + gt) : 0;
            it2 = huv[gi];
            rt2 = hr[gi];
        }

        {
            const float* ua = s.u_att + gid * D;
            #pragma unroll
            for (int mt = 0; mt < 2; mt++)
                #pragma unroll
                for (int nt = 0; nt < 4; nt++) {
                    int c = nbk + 8 * nt + 2 * q;
                    float b0 = ua[c], b1 = ua[c + 1];
                    acc[mt][nt][0] = b0; acc[mt][nt][1] = b1;
                    acc[mt][nt][2] = b0; acc[mt][nt][3] = b1;
                }
        }
        run_mma_gemm_cb(Og, bcA1, acc, mb, lane);
        store_relu_f16(Hg, acc, mb, nbk, g, q);

        if (gt < L_HIST) {
            s.items[gid * L_HIST + gt] = it2;
            s.rats[gid * L_HIST + gt]  = rt2;
        }
        GROUP_BAR();

        // ---- phase 3: GEMM C (B from smem) -> lpart ----
        #pragma unroll
        for (int mt = 0; mt < 2; mt++)
            #pragma unroll
            for (int nt = 0; nt < 4; nt++) {
                int c = nbk + 8 * nt + 2 * q;
                float b0 = s.b_a2[c], b1 = s.b_a2[c + 1];
                acc[mt][nt][0] = b0; acc[mt][nt][1] = b1;
                acc[mt][nt][2] = b0; acc[mt][nt][3] = b1;
            }
        run_mma_gemm_sb(Hg, s.A2s, acc, mb, nbk, lane);
        {
            float p[2][2] = {{0.f, 0.f}, {0.f, 0.f}};
            #pragma unroll
            for (int mt = 0; mt < 2; mt++)
                #pragma unroll
                for (int nt = 0; nt < 4; nt++) {
                    int c = nbk + 8 * nt + 2 * q;
                    float w0 = s.a3s[c], w1 = s.a3s[c + 1];
                    p[mt][0] = fmaf(fmaxf(acc[mt][nt][0], 0.f), w0, p[mt][0]);
                    p[mt][0] = fmaf(fmaxf(acc[mt][nt][1], 0.f), w1, p[mt][0]);
                    p[mt][1] = fmaf(fmaxf(acc[mt][nt][2], 0.f), w0, p[mt][1]);
                    p[mt][1] = fmaf(fmaxf(acc[mt][nt][3], 0.f), w1, p[mt][1]);
                }
            #pragma unroll
            for (int off = 1; off <= 2; off <<= 1) {
                #pragma unroll
                for (int mt = 0; mt < 2; mt++) {
                    p[mt][0] += __shfl_xor_sync(0xffffffffu, p[mt][0], off);
                    p[mt][1] += __shfl_xor_sync(0xffffffffu, p[mt][1], off);
                }
            }
            if (q == 0) {
                #pragma unroll
                for (int mt = 0; mt < 2; mt++) {
                    int gr = rowbase + mb + 16 * mt + g;
                    s.lpart[gr * 2 + cw]       = p[mt][0];
                    s.lpart[(gr + 8) * 2 + cw] = p[mt][1];
                }
            }
        }
        GROUP_BAR();   // all GEMM C ldsm reads of Hg complete past this point

        // ---- phase 4: cp.async next h_pre rows DIRECTLY into Hg + next
        //      u_att into s.u_att[gid]; softmax on group's warp 0 ----
        for (int c = gt; c < L_HIST * 8; c += 128) {
            int v = c >> 3, k8 = (c & 7) << 3;
            cp_async16(hbuf_u32 + (uint32_t)((rowbase + v) * LDW + k8) * 2,
                       g_h_pre + (size_t)s.items[gid * L_HIST + v] * D + k8);
        }
        if (gt < 16) {
            int src = pf ? (nb2 + gid) : 0;
            cp_async16(uatt_u32 + (uint32_t)(gid * D + gt * 4) * 4,
                       g_u_att + (size_t)src * D + gt * 4);
        }
        asm volatile("cp.async.commit_group;" ::: "memory");

        if (wg == 0) {
            int r1 = rowbase + lane;
            float v1 = s.lpart[r1 * 2] + s.lpart[r1 * 2 + 1];
            float v2 = -1e30f;
            if (lane + 32 < L_HIST)
                v2 = s.lpart[(r1 + 32) * 2] + s.lpart[(r1 + 32) * 2 + 1];
            float m = fmaxf(v1, v2);
            #pragma unroll
            for (int off = 16; off >= 1; off >>= 1)
                m = fmaxf(m, __shfl_xor_sync(0xffffffffu, m, off));
            float e1 = __expf(v1 - m);
            float e2 = (lane + 32 < L_HIST) ? __expf(v2 - m) : 0.f;
            float ssum = e1 + e2;
            #pragma unroll
            for (int off = 16; off >= 1; off >>= 1)
                ssum += __shfl_xor_sync(0xffffffffu, ssum, off);
            float inv = 1.f / ssum;
            s.attw[r1] = e1 * inv;
            if (lane + 32 < L_HIST) s.attw[r1 + 32] = e2 * inv;
        }
        GROUP_BAR();

        // ---- phase 5: out partials (re-read own Og tile) ----
        {
            float oc[8] = {0.f, 0.f, 0.f, 0.f, 0.f, 0.f, 0.f, 0.f};
            #pragma unroll
            for (int mt = 0; mt < 2; mt++)
                #pragma unroll
                for (int rr = 0; rr < 2; rr++) {
                    int lr = mb + 16 * mt + g + 8 * rr;
                    if (lr < L_HIST) {
                        float w = s.attw[rowbase + lr];
                        #pragma unroll
                        for (int nt = 0; nt < 4; nt++) {
                            int c = nbk + 8 * nt + 2 * q;
                            float2 ov = __half22float2(
                                *(const __half2*)(Og + lr * LDW + c));
                            oc[2 * nt]     = fmaf(w, ov.x, oc[2 * nt]);
                            oc[2 * nt + 1] = fmaf(w, ov.y, oc[2 * nt + 1]);
                        }
                    }
                }
            #pragma unroll
            for (int off = 4; off <= 16; off <<= 1)
                #pragma unroll
                for (int i = 0; i < 8; i++)
                    oc[i] += __shfl_xor_sync(0xffffffffu, oc[i], off);
            if (g == 0) {
                int basep = (gid * 2 + (mb >> 5)) * D;
                #pragma unroll
                for (int nt = 0; nt < 4; nt++) {
                    s.outp[basep + nbk + 8 * nt + 2 * q]     = oc[2 * nt];
                    s.outp[basep + nbk + 8 * nt + 2 * q + 1] = oc[2 * nt + 1];
                }
            }
        }
        GROUP_BAR();

        // ---- phase 6: final store ; wait staged data ----
        if (gt < D) {
            out[(size_t)node_g * D + gt] =
                s.outp[(gid * 2) * D + gt] + s.outp[(gid * 2 + 1) * D + gt];
        }
        asm volatile("cp.async.wait_group 0;" ::: "memory");
        GROUP_BAR();
    }
}

// ---------------------------------------------------------------------------
extern "C" void kernel_launch(void* const* d_in, const int* in_sizes, int n_in,
                              void* d_out, int out_size)
{
    const int*   nodes = (const int*)d_in[0];
    const int*   huv   = (const int*)d_in[1];
    const int*   hr    = (const int*)d_in[2];
    const float* v2e   = (const float*)d_in[3];
    const float* u2e   = (const float*)d_in[4];
    const float* r2e   = (const float*)d_in[5];
    const float* w1w   = (const float*)d_in[6];
    const float* w1b   = (const float*)d_in[7];
    const float* w2w   = (const float*)d_in[8];
    const float* w2b   = (const float*)d_in[9];
    const float* a1w   = (const float*)d_in[10];
    const float* a1b   = (const float*)d_in[11];
    const float* a2w   = (const float*)d_in[12];
    const float* a2b   = (const float*)d_in[13];
    const float* a3w   = (const float*)d_in[14];
    const float* a3b   = (const float*)d_in[15];
    float* out = (float*)d_out;

    (void)in_sizes; (void)n_in; (void)out_size; (void)a3b;

    cudaFuncSetAttribute(uv_agg_main,
                         cudaFuncAttributeMaxDynamicSharedMemorySize,
                         (int)sizeof(Smem));

    pre_h_kernel<<<(NI + MROWS - 1) / MROWS, 256>>>(v2e, w1w, r2e, w1b);
    pre_u_kernel<<<B_NODES / 64, 256>>>(nodes, u2e, a1w, a1b);
    uv_agg_main<<<GRID, 256, sizeof(Smem)>>>(huv, hr,
                                             w2w, w2b, a1w,
                                             a2w, a2b, a3w, out);
}

// round 15
// speedup vs baseline: 1.2281x; 1.2281x over previous
#include <cuda_runtime.h>
#include <cuda_fp16.h>
#include <cstdint>

#define B_NODES 16384
#define L_HIST  50
#define D       64
#define LDW     72       // halves per row (144 B) for all f16 matrices
#define NPI     2        // nodes per iteration (one per 4-warp group)
#define MROWS   128
#define VROWS   100
#define NI      100000
#define NR      5
#define GRID    296
#define STRIDE  (GRID * NPI)
#define NTILES  ((NI + MROWS - 1) / MROWS)   // 782

// Scratch (module-static device memory; allocation-free at launch time)
__device__ __half g_h_pre[NI * D];    // f16( f16MMA(v2e) @ W1_top )  (12.8 MB, L2)
__device__ __half g_r_pre[NR * D];    // f16( r2e_w @ W1_bot + b1 )

// ---------------------------------------------------------------------------
// mma + ldmatrix helpers
// ---------------------------------------------------------------------------
__device__ __forceinline__ void mma_f16(float (&d)[4],
                                        uint32_t a0, uint32_t a1, uint32_t a2, uint32_t a3,
                                        uint32_t b0, uint32_t b1)
{
    asm volatile(
        "mma.sync.aligned.m16n8k16.row.col.f32.f16.f16.f32 "
        "{%0,%1,%2,%3}, {%4,%5,%6,%7}, {%8,%9}, {%0,%1,%2,%3};\n"
        : "+f"(d[0]), "+f"(d[1]), "+f"(d[2]), "+f"(d[3])
        : "r"(a0), "r"(a1), "r"(a2), "r"(a3), "r"(b0), "r"(b1));
}

__device__ __forceinline__ void ldsm_x4(uint32_t (&r)[4], uint32_t addr) {
    asm volatile("ldmatrix.sync.aligned.m8n8.x4.shared.b16 {%0,%1,%2,%3}, [%4];"
                 : "=r"(r[0]), "=r"(r[1]), "=r"(r[2]), "=r"(r[3]) : "r"(addr));
}

// Load a warp's B fragments (n-slice nbk..nbk+31, all k) into registers.
__device__ __forceinline__ void load_bfrag(
    const __half* __restrict__ Wt, uint32_t (&bc)[4][8], int nbk, int lane)
{
    uint32_t bbase = (uint32_t)__cvta_generic_to_shared(Wt)
                   + (uint32_t)((((nbk + ((lane >> 4) << 3) + (lane & 7)) * LDW)
                                 + (((lane >> 3) & 1) << 3)) << 1);
    #pragma unroll
    for (int ks = 0; ks < 4; ks++) {
        uint32_t b0[4], b1[4];
        ldsm_x4(b0, bbase + 32 * ks);
        ldsm_x4(b1, bbase + 32 * ks + 32 * LDW);
        bc[ks][0] = b0[0]; bc[ks][1] = b0[1]; bc[ks][2] = b0[2]; bc[ks][3] = b0[3];
        bc[ks][4] = b1[0]; bc[ks][5] = b1[1]; bc[ks][6] = b1[2]; bc[ks][7] = b1[3];
    }
}

// 64x64x64 GEMM slice with register-cached B fragments; warp tile 32x32.
__device__ __forceinline__ void run_mma_gemm_cb(
    const __half* __restrict__ Ab, const uint32_t (&bc)[4][8],
    float (&acc)[2][4][4], int mb, int lane)
{
    uint32_t abase = (uint32_t)__cvta_generic_to_shared(Ab)
                   + (uint32_t)((((mb + (lane & 15)) * LDW) + ((lane >> 4) << 3)) << 1);
    #pragma unroll
    for (int ks = 0; ks < 4; ks++) {
        uint32_t a0[4], a1[4];
        ldsm_x4(a0, abase + 32 * ks);
        ldsm_x4(a1, abase + 32 * ks + 32 * LDW);
        mma_f16(acc[0][0], a0[0], a0[1], a0[2], a0[3], bc[ks][0], bc[ks][1]);
        mma_f16(acc[0][1], a0[0], a0[1], a0[2], a0[3], bc[ks][2], bc[ks][3]);
        mma_f16(acc[0][2], a0[0], a0[1], a0[2], a0[3], bc[ks][4], bc[ks][5]);
        mma_f16(acc[0][3], a0[0], a0[1], a0[2], a0[3], bc[ks][6], bc[ks][7]);
        mma_f16(acc[1][0], a1[0], a1[1], a1[2], a1[3], bc[ks][0], bc[ks][1]);
        mma_f16(acc[1][1], a1[0], a1[1], a1[2], a1[3], bc[ks][2], bc[ks][3]);
        mma_f16(acc[1][2], a1[0], a1[1], a1[2], a1[3], bc[ks][4], bc[ks][5]);
        mma_f16(acc[1][3], a1[0], a1[1], a1[2], a1[3], bc[ks][6], bc[ks][7]);
    }
}

// Same but with B from shared memory (GEMM C / pre_h).
__device__ __forceinline__ void run_mma_gemm_sb(
    const __half* __restrict__ Ab, const __half* __restrict__ Wt,
    float (&acc)[2][4][4], int mb, int nbk, int lane)
{
    uint32_t abase = (uint32_t)__cvta_generic_to_shared(Ab)
                   + (uint32_t)((((mb + (lane & 15)) * LDW) + ((lane >> 4) << 3)) << 1);
    uint32_t bbase = (uint32_t)__cvta_generic_to_shared(Wt)
                   + (uint32_t)((((nbk + ((lane >> 4) << 3) + (lane & 7)) * LDW)
                                 + (((lane >> 3) & 1) << 3)) << 1);
    #pragma unroll
    for (int ks = 0; ks < 4; ks++) {
        uint32_t a0[4], a1[4], b0[4], b1[4];
        ldsm_x4(a0, abase + 32 * ks);
        ldsm_x4(a1, abase + 32 * ks + 32 * LDW);
        ldsm_x4(b0, bbase + 32 * ks);
        ldsm_x4(b1, bbase + 32 * ks + 32 * LDW);
        mma_f16(acc[0][0], a0[0], a0[1], a0[2], a0[3], b0[0], b0[1]);
        mma_f16(acc[0][1], a0[0], a0[1], a0[2], a0[3], b0[2], b0[3]);
        mma_f16(acc[0][2], a0[0], a0[1], a0[2], a0[3], b1[0], b1[1]);
        mma_f16(acc[0][3], a0[0], a0[1], a0[2], a0[3], b1[2], b1[3]);
        mma_f16(acc[1][0], a1[0], a1[1], a1[2], a1[3], b0[0], b0[1]);
        mma_f16(acc[1][1], a1[0], a1[1], a1[2], a1[3], b0[2], b0[3]);
        mma_f16(acc[1][2], a1[0], a1[1], a1[2], a1[3], b1[0], b1[1]);
        mma_f16(acc[1][3], a1[0], a1[1], a1[2], a1[3], b1[2], b1[3]);
    }
}

// relu + f16 store of the 32x32 warp tile into Out[64][LDW]
__device__ __forceinline__ void store_relu_f16(
    __half* __restrict__ Out, float (&acc)[2][4][4],
    int mb, int nbk, int g, int q)
{
    #pragma unroll
    for (int mt = 0; mt < 2; mt++)
        #pragma unroll
        for (int nt = 0; nt < 4; nt++) {
            int r0 = mb + 16 * mt + g;
            int c  = nbk + 8 * nt + 2 * q;
            __half2 v0 = __floats2half2_rn(fmaxf(acc[mt][nt][0], 0.f),
                                           fmaxf(acc[mt][nt][1], 0.f));
            __half2 v1 = __floats2half2_rn(fmaxf(acc[mt][nt][2], 0.f),
                                           fmaxf(acc[mt][nt][3], 0.f));
            *(__half2*)(Out + r0 * LDW + c)       = v0;
            *(__half2*)(Out + (r0 + 8) * LDW + c) = v1;
        }
}

__device__ __forceinline__ void cp_async16(uint32_t dst, const void* src) {
    asm volatile("cp.async.cg.shared.global [%0], [%1], 16;"
                 :: "r"(dst), "l"(src) : "memory");
}

// ---------------------------------------------------------------------------
// Precompute: persistent, double-buffered pre_h
//   h_pre = f16( f16MMA(v2e @ W1_top) ); block 0 also computes r_pre (f16)
// ---------------------------------------------------------------------------
struct __align__(16) PreSmem {
    __half W1t[D * LDW];            // W1_top^T f16 [n][k]
    float  Af32[2][MROWS * D];      // double-buffered f32 staging (2 x 32 KB)
    __half Af16[MROWS * LDW];       // converted MMA operand
};

__global__ void __launch_bounds__(256, 2)
pre_h_kernel(const float* __restrict__ v2e,
             const float* __restrict__ w1,
             const float* __restrict__ r2e,
             const float* __restrict__ b1)
{
    extern __shared__ __align__(16) char praw[];
    PreSmem& s = *reinterpret_cast<PreSmem*>(praw);
    const int t = threadIdx.x;
    const int wid = t >> 5, lane = t & 31;
    const int g = lane >> 2, q = lane & 3;
    const int mb = (wid & 3) * 32, nbk = (wid >> 2) * 32;
    const uint32_t a32_0 = (uint32_t)__cvta_generic_to_shared(s.Af32[0]);
    const uint32_t a32_1 = (uint32_t)__cvta_generic_to_shared(s.Af32[1]);

    // one-time: W1_top^T into smem (f16)
    for (int i = t; i < D * D; i += 256) {
        int n = i >> 6, k = i & 63;
        s.W1t[n * LDW + k] = __float2half_rn(w1[k * D + n]);
    }

    // block 0: r_pre (tiny, f32 math)
    if (blockIdx.x == 0) {
        for (int i = t; i < NR * D; i += 256) {
            int r = i >> 6, j = i & 63;
            float a = b1[j];
            #pragma unroll 16
            for (int k = 0; k < D; k++)
                a = fmaf(r2e[r * D + k], w1[(D + k) * D + j], a);
            g_r_pre[i] = __float2half_rn(a);
        }
    }

    // prefetch first tile into buf 0
    int tile = blockIdx.x;
    {
        for (int c = t; c < MROWS * 16; c += 256) {
            int r = c >> 4, c4 = c & 15;
            int row = tile * MROWS + r; if (row >= NI) row = NI - 1;
            cp_async16(a32_0 + (uint32_t)c * 16, v2e + (size_t)row * D + c4 * 4);
        }
        asm volatile("cp.async.commit_group;" ::: "memory");
    }

    int buf = 0;
    for (; tile < NTILES; tile += gridDim.x, buf ^= 1) {
        const int ntile = tile + gridDim.x;
        const bool has_next = ntile < NTILES;

        // prefetch next tile into the other buffer (group stays in flight)
        if (has_next) {
            uint32_t dst = buf ? a32_0 : a32_1;
            for (int c = t; c < MROWS * 16; c += 256) {
                int r = c >> 4, c4 = c & 15;
                int row = ntile * MROWS + r; if (row >= NI) row = NI - 1;
                cp_async16(dst + (uint32_t)c * 16, v2e + (size_t)row * D + c4 * 4);
            }
            asm volatile("cp.async.commit_group;" ::: "memory");
            asm volatile("cp.async.wait_group 1;" ::: "memory");
        } else {
            asm volatile("cp.async.wait_group 0;" ::: "memory");
        }
        __syncthreads();

        // convert current buffer f32 -> f16 operand
        {
            const float4* src = (const float4*)s.Af32[buf];
            for (int i = t; i < MROWS * 16; i += 256) {
                int r = i >> 4, c4 = i & 15;
                float4 v = src[i];
                uint2 o;
                *(__half2*)&o.x = __floats2half2_rn(v.x, v.y);
                *(__half2*)&o.y = __floats2half2_rn(v.z, v.w);
                *(uint2*)(s.Af16 + r * LDW + c4 * 4) = o;
            }
        }
        __syncthreads();

        // MMA + store
        float acc[2][4][4];
        #pragma unroll
        for (int mt = 0; mt < 2; mt++)
            #pragma unroll
            for (int nt = 0; nt < 4; nt++)
                #pragma unroll
                for (int e = 0; e < 4; e++) acc[mt][nt][e] = 0.f;
        run_mma_gemm_sb(s.Af16, s.W1t, acc, mb, nbk, lane);

        const int base = tile * MROWS;
        #pragma unroll
        for (int mt = 0; mt < 2; mt++)
            #pragma unroll
            for (int nt = 0; nt < 4; nt++) {
                int r0 = base + mb + 16 * mt + g;
                int c  = nbk + 8 * nt + 2 * q;
                if (r0 < NI)
                    *(__half2*)(g_h_pre + (size_t)r0 * D + c) =
                        __floats2half2_rn(acc[mt][nt][0], acc[mt][nt][1]);
                if (r0 + 8 < NI)
                    *(__half2*)(g_h_pre + (size_t)(r0 + 8) * D + c) =
                        __floats2half2_rn(acc[mt][nt][2], acc[mt][nt][3]);
            }
        __syncthreads();   // Af16 consumed before next convert overwrites it
    }
}

// ---------------------------------------------------------------------------
// Main persistent kernel: two independent 4-warp groups per CTA, one node each
// (R13 winner, verbatim)
// ---------------------------------------------------------------------------
struct __align__(16) Smem {
    __half W2s[D * LDW];        // w_r2_w^T   [n][k]
    __half A1ts[D * LDW];       // att1_w top^T [n][k]
    __half A2s[D * LDW];        // att2_w^T   [n][k]
    __half Hbuf[MROWS * LDW];   // activations; rows [gid*64, gid*64+64)
    __half Obuf[MROWS * LDW];   // o_history f16
    __half stage[VROWS * D];    // staged h_pre rows; [gid*50, gid*50+50)
    __half A1Bh[D * D];         // att1_w rows 64..127 (f16, [k][j])
    __half rpre[NR * D];        // f16
    float  a3s[D];
    float  b_r2[D];
    float  b_a2[D];
    float  b_a1[D];
    float  uvs[NPI * D];
    float  u_att[NPI * D];
    float  lpart[MROWS * 2];    // per-row logit partials (2 col-warp-groups)
    float  attw[MROWS];
    float  outp[4 * D];         // [gid*2 + mbblk][64]
    int    items[VROWS];        // [gid*50 + l]
    int    rats[VROWS];
    int    nodesbuf[NPI];
};

#define GROUP_BAR() asm volatile("bar.sync %0, 128;" :: "r"(gid + 1) : "memory")

__global__ void __launch_bounds__(256, 2)
uv_agg_main(const int* __restrict__ nodes,
            const int* __restrict__ huv,
            const int* __restrict__ hr,
            const float* __restrict__ u2e,
            const float* __restrict__ w2w, const float* __restrict__ w2b,
            const float* __restrict__ a1w, const float* __restrict__ a1b,
            const float* __restrict__ a2w, const float* __restrict__ a2b,
            const float* __restrict__ a3w, const float* __restrict__ a3b,
            float* __restrict__ out)
{
    extern __shared__ __align__(16) char sraw[];
    Smem& s = *reinterpret_cast<Smem*>(sraw);
    const int t    = threadIdx.x;
    const int gid  = t >> 7;          // group (node) 0/1
    const int gt   = t & 127;         // thread-in-group
    const int wg   = (t >> 5) & 3;    // warp-in-group 0..3
    const int lane = t & 31;
    const int g    = lane >> 2;
    const int q    = lane & 3;
    const int mb   = (wg & 1) * 32;   // row-block within the node's 64-row tile
    const int nbk  = (wg >> 1) * 32;  // col-block
    const int cw   = wg >> 1;
    const int rowbase = gid * 64;     // node's row base in Hbuf/Obuf
    const uint32_t stage_u32 = (uint32_t)__cvta_generic_to_shared(s.stage);

    __half* Hg = s.Hbuf + rowbase * LDW;
    __half* Og = s.Obuf + rowbase * LDW;

    // ---- one-time weight staging (all 256 threads) ----
    for (int i = t; i < 3 * D * D; i += 256) {
        int mat = i >> 12, w = i & 4095;
        int n = w >> 6, k = w & 63;
        const float* W = (mat == 0) ? w2w : (mat == 1) ? a1w : a2w;
        __half h = __float2half_rn(W[k * D + n]);
        if (mat == 0)      s.W2s [n * LDW + k] = h;
        else if (mat == 1) s.A1ts[n * LDW + k] = h;
        else               s.A2s [n * LDW + k] = h;
    }
    for (int i = t; i < D * D; i += 256)
        s.A1Bh[i] = __float2half_rn(a1w[D * D + i]);
    if (t < D) {
        s.a3s[t]  = a3w[t];
        s.b_r2[t] = w2b[t];
        s.b_a1[t] = a1b[t];
        s.b_a2[t] = a2b[t];
    }
    for (int i = t; i < NR * D; i += 256) s.rpre[i] = g_r_pre[i];
    // zero Hbuf/Obuf so garbage f16 rows can never be NaN/inf
    for (int i = t; i < MROWS * LDW / 2; i += 256) {
        ((uint32_t*)s.Hbuf)[i] = 0u;
        ((uint32_t*)s.Obuf)[i] = 0u;
    }
    __syncthreads();

    // ---- per-warp register B caches (GEMM A + GEMM B) ----
    uint32_t bcW2[4][8], bcA1[4][8];
    load_bfrag(s.W2s,  bcW2, nbk, lane);
    load_bfrag(s.A1ts, bcA1, nbk, lane);

    // ---- prologue: iter-0 indices + stage + uv (all threads) ----
    const int nb0 = blockIdx.x * NPI;
    if (t < VROWS) {
        int node = (t >= L_HIST);
        int l = t - L_HIST * node;
        int gi = (nb0 + node) * L_HIST + l;
        s.items[node * L_HIST + l] = huv[gi];
        s.rats[node * L_HIST + l]  = hr[gi];
    }
    if (t >= 200 && t < 200 + NPI)
        s.nodesbuf[t - 200] = nodes[nb0 + t - 200];
    __syncthreads();
    for (int c = t; c < VROWS * 8; c += 256) {
        int v = c >> 3, k8 = (c & 7) << 3;
        cp_async16(stage_u32 + (uint32_t)(v * D + k8) * 2,
                   g_h_pre + (size_t)s.items[v] * D + k8);
    }
    asm volatile("cp.async.commit_group;" ::: "memory");
    if (t < NPI * D)
        s.uvs[t] = u2e[(size_t)s.nodesbuf[t >> 6] * D + (t & 63)];
    asm volatile("cp.async.wait_group 0;" ::: "memory");
    __syncthreads();

    // ================= per-group pipeline (groups desynchronized) =========
    for (int nb = nb0; nb < B_NODES; nb += STRIDE) {
        const int node_g  = nb + gid;
        const int nb2     = nb + STRIDE;
        const bool pf     = nb2 < B_NODES;

        // ---- phase 0: stage -> Hbuf (relu(h+r), f16) ; u_att ----
        {
            const __half2 zero2 = __floats2half2_rn(0.f, 0.f);
            for (int c = gt; c < L_HIST * 8; c += 128) {
                int v = c >> 3, c8 = (c & 7) << 3;
                const __half* sp = s.stage + (gid * L_HIST + v) * D + c8;
                const __half* rp = s.rpre + s.rats[gid * L_HIST + v] * D + c8;
                uint2 hv  = *(const uint2*)sp;
                uint2 hv2 = *(const uint2*)(sp + 4);
                uint2 rv  = *(const uint2*)rp;
                uint2 rv2 = *(const uint2*)(rp + 4);
                __half2 o[4];
                o[0] = __hmax2(__hadd2(*(__half2*)&hv.x,  *(__half2*)&rv.x),  zero2);
                o[1] = __hmax2(__hadd2(*(__half2*)&hv.y,  *(__half2*)&rv.y),  zero2);
                o[2] = __hmax2(__hadd2(*(__half2*)&hv2.x, *(__half2*)&rv2.x), zero2);
                o[3] = __hmax2(__hadd2(*(__half2*)&hv2.y, *(__half2*)&rv2.y), zero2);
                *(float4*)(Hg + v * LDW + c8) = *(float4*)o;
            }
        }
        if (gt < D) {
            float acc0 = s.b_a1[gt];
            const float* uv = s.uvs + gid * D;
            #pragma unroll 16
            for (int k = 0; k < D; k++)
                acc0 = fmaf(uv[k], __half2float(s.A1Bh[k * D + gt]), acc0);
            s.u_att[gid * D + gt] = acc0;
        }
        GROUP_BAR();

        float acc[2][4][4];

        // ---- phase 1: GEMM A (cached W2) -> Og ----
        #pragma unroll
        for (int mt = 0; mt < 2; mt++)
            #pragma unroll
            for (int nt = 0; nt < 4; nt++) {
                int c = nbk + 8 * nt + 2 * q;
                float b0 = s.b_r2[c], b1 = s.b_r2[c + 1];
                acc[mt][nt][0] = b0; acc[mt][nt][1] = b1;
                acc[mt][nt][2] = b0; acc[mt][nt][3] = b1;
            }
        run_mma_gemm_cb(Hg, bcW2, acc, mb, lane);
        store_relu_f16(Og, acc, mb, nbk, g, q);
        GROUP_BAR();

        // ---- phase 2: idx prefetch (regs) ; GEMM B (cached A1t) -> Hg ----
        int it2 = 0, rt2 = 0, nd2 = 0;
        if (gt < L_HIST) {
            int gi = pf ? ((nb2 + gid) * L_HIST + gt) : 0;
            it2 = huv[gi];
            rt2 = hr[gi];
        }
        if (gt == 120)
            nd2 = nodes[pf ? (nb2 + gid) : 0];

        {
            const float* ua = s.u_att + gid * D;
            #pragma unroll
            for (int mt = 0; mt < 2; mt++)
                #pragma unroll
                for (int nt = 0; nt < 4; nt++) {
                    int c = nbk + 8 * nt + 2 * q;
                    float b0 = ua[c], b1 = ua[c + 1];
                    acc[mt][nt][0] = b0; acc[mt][nt][1] = b1;
                    acc[mt][nt][2] = b0; acc[mt][nt][3] = b1;
                }
        }
        run_mma_gemm_cb(Og, bcA1, acc, mb, lane);
        store_relu_f16(Hg, acc, mb, nbk, g, q);

        if (gt < L_HIST) {
            s.items[gid * L_HIST + gt] = it2;
            s.rats[gid * L_HIST + gt]  = rt2;
        }
        if (gt == 120) s.nodesbuf[gid] = nd2;
        GROUP_BAR();

        // ---- phase 3: cp.async stage(next) ; uv prefetch ; GEMM C ----
        for (int c = gt; c < L_HIST * 8; c += 128) {
            int v = c >> 3, k8 = (c & 7) << 3;
            int sv = gid * L_HIST + v;
            cp_async16(stage_u32 + (uint32_t)(sv * D + k8) * 2,
                       g_h_pre + (size_t)s.items[sv] * D + k8);
        }
        asm volatile("cp.async.commit_group;" ::: "memory");
        float uvreg = 0.f;
        if (gt < D)
            uvreg = u2e[(size_t)s.nodesbuf[gid] * D + gt];

        #pragma unroll
        for (int mt = 0; mt < 2; mt++)
            #pragma unroll
            for (int nt = 0; nt < 4; nt++) {
                int c = nbk + 8 * nt + 2 * q;
                float b0 = s.b_a2[c], b1 = s.b_a2[c + 1];
                acc[mt][nt][0] = b0; acc[mt][nt][1] = b1;
                acc[mt][nt][2] = b0; acc[mt][nt][3] = b1;
            }
        run_mma_gemm_sb(Hg, s.A2s, acc, mb, nbk, lane);
        {
            float p[2][2] = {{0.f, 0.f}, {0.f, 0.f}};
            #pragma unroll
            for (int mt = 0; mt < 2; mt++)
                #pragma unroll
                for (int nt = 0; nt < 4; nt++) {
                    int c = nbk + 8 * nt + 2 * q;
                    float w0 = s.a3s[c], w1 = s.a3s[c + 1];
                    p[mt][0] = fmaf(fmaxf(acc[mt][nt][0], 0.f), w0, p[mt][0]);
                    p[mt][0] = fmaf(fmaxf(acc[mt][nt][1], 0.f), w1, p[mt][0]);
                    p[mt][1] = fmaf(fmaxf(acc[mt][nt][2], 0.f), w0, p[mt][1]);
                    p[mt][1] = fmaf(fmaxf(acc[mt][nt][3], 0.f), w1, p[mt][1]);
                }
            #pragma unroll
            for (int off = 1; off <= 2; off <<= 1) {
                #pragma unroll
                for (int mt = 0; mt < 2; mt++) {
                    p[mt][0] += __shfl_xor_sync(0xffffffffu, p[mt][0], off);
                    p[mt][1] += __shfl_xor_sync(0xffffffffu, p[mt][1], off);
                }
            }
            if (q == 0) {
                #pragma unroll
                for (int mt = 0; mt < 2; mt++) {
                    int gr = rowbase + mb + 16 * mt + g;
                    s.lpart[gr * 2 + cw]       = p[mt][0];
                    s.lpart[(gr + 8) * 2 + cw] = p[mt][1];
                }
            }
        }
        GROUP_BAR();

        // ---- phase 4: softmax (group's warp 0) ; stash uv ----
        if (wg == 0) {
            int r1 = rowbase + lane;
            float v1 = s.lpart[r1 * 2] + s.lpart[r1 * 2 + 1];
            float v2 = -1e30f;
            if (lane + 32 < L_HIST)
                v2 = s.lpart[(r1 + 32) * 2] + s.lpart[(r1 + 32) * 2 + 1];
            float m = fmaxf(v1, v2);
            #pragma unroll
            for (int off = 16; off >= 1; off >>= 1)
                m = fmaxf(m, __shfl_xor_sync(0xffffffffu, m, off));
            float e1 = __expf(v1 - m);
            float e2 = (lane + 32 < L_HIST) ? __expf(v2 - m) : 0.f;
            float ssum = e1 + e2;
            #pragma unroll
            for (int off = 16; off >= 1; off >>= 1)
                ssum += __shfl_xor_sync(0xffffffffu, ssum, off);
            float inv = 1.f / ssum;
            s.attw[r1] = e1 * inv;
            if (lane + 32 < L_HIST) s.attw[r1 + 32] = e2 * inv;
        }
        if (gt < D) s.uvs[gid * D + gt] = uvreg;
        GROUP_BAR();

        // ---- phase 5: out partials (re-read own Og tile) ----
        {
            float oc[8] = {0.f, 0.f, 0.f, 0.f, 0.f, 0.f, 0.f, 0.f};
            #pragma unroll
            for (int mt = 0; mt < 2; mt++)
                #pragma unroll
                for (int rr = 0; rr < 2; rr++) {
                    int lr = mb + 16 * mt + g + 8 * rr;
                    if (lr < L_HIST) {
                        float w = s.attw[rowbase + lr];
                        #pragma unroll
                        for (int nt = 0; nt < 4; nt++) {
                            int c = nbk + 8 * nt + 2 * q;
                            float2 ov = __half22float2(
                                *(const __half2*)(Og + lr * LDW + c));
                            oc[2 * nt]     = fmaf(w, ov.x, oc[2 * nt]);
                            oc[2 * nt + 1] = fmaf(w, ov.y, oc[2 * nt + 1]);
                        }
                    }
                }
            #pragma unroll
            for (int off = 4; off <= 16; off <<= 1)
                #pragma unroll
                for (int i = 0; i < 8; i++)
                    oc[i] += __shfl_xor_sync(0xffffffffu, oc[i], off);
            if (g == 0) {
                int basep = (gid * 2 + (mb >> 5)) * D;
                #pragma unroll
                for (int nt = 0; nt < 4; nt++) {
                    s.outp[basep + nbk + 8 * nt + 2 * q]     = oc[2 * nt];
                    s.outp[basep + nbk + 8 * nt + 2 * q + 1] = oc[2 * nt + 1];
                }
            }
        }
        GROUP_BAR();

        // ---- phase 6: final store ; wait staged data ----
        if (gt < D) {
            out[(size_t)node_g * D + gt] =
                s.outp[(gid * 2) * D + gt] + s.outp[(gid * 2 + 1) * D + gt];
        }
        asm volatile("cp.async.wait_group 0;" ::: "memory");
        GROUP_BAR();
    }
}

// ---------------------------------------------------------------------------
extern "C" void kernel_launch(void* const* d_in, const int* in_sizes, int n_in,
                              void* d_out, int out_size)
{
    const int*   nodes = (const int*)d_in[0];
    const int*   huv   = (const int*)d_in[1];
    const int*   hr    = (const int*)d_in[2];
    const float* v2e   = (const float*)d_in[3];
    const float* u2e   = (const float*)d_in[4];
    const float* r2e   = (const float*)d_in[5];
    const float* w1w   = (const float*)d_in[6];
    const float* w1b   = (const float*)d_in[7];
    const float* w2w   = (const float*)d_in[8];
    const float* w2b   = (const float*)d_in[9];
    const float* a1w   = (const float*)d_in[10];
    const float* a1b   = (const float*)d_in[11];
    const float* a2w   = (const float*)d_in[12];
    const float* a2b   = (const float*)d_in[13];
    const float* a3w   = (const float*)d_in[14];
    const float* a3b   = (const float*)d_in[15];
    float* out = (float*)d_out;

    (void)in_sizes; (void)n_in; (void)out_size; (void)a3b;

    cudaFuncSetAttribute(pre_h_kernel,
                         cudaFuncAttributeMaxDynamicSharedMemorySize,
                         (int)sizeof(PreSmem));
    cudaFuncSetAttribute(uv_agg_main,
                         cudaFuncAttributeMaxDynamicSharedMemorySize,
                         (int)sizeof(Smem));

    pre_h_kernel<<<GRID, 256, sizeof(PreSmem)>>>(v2e, w1w, r2e, w1b);
    uv_agg_main<<<GRID, 256, sizeof(Smem)>>>(nodes, huv, hr, u2e,
                                             w2w, w2b, a1w, a1b,
                                             a2w, a2b, a3w, a3b, out);
}